// round 1
// baseline (speedup 1.0000x reference)
#include <cuda_runtime.h>
#include <math.h>

#define NPTS 32768
#define RS   68      // padded row stride (floats) for transposed activation tiles
#define TILE 64

__device__ int g_cnt[8];
__device__ int g_list[8 * NPTS];

// ---------------- smem layout (float offsets) ----------------
#define SM_XST   0
#define SM_X0T   (256 * RS)
#define SM_DET   (SM_X0T + 112 * RS)
#define SM_WS    (SM_DET + 28 * RS)
#define SM_WD    (SM_WS + 2 * 32 * 256)
#define SM_WC2   (SM_WD + 256)
#define SM_DENS  (SM_WC2 + 390)
#define SM_GIDX  (SM_DENS + 64)
#define SM_TOTALF (SM_GIDX + 64)
#define SMEM_BYTES (SM_TOTALF * 4)

// ---------------- packed f32x2 helpers ----------------
__device__ __forceinline__ unsigned long long dup2(float v) {
    unsigned long long r;
    asm("mov.b64 %0, {%1, %1};" : "=l"(r) : "f"(v));
    return r;
}
__device__ __forceinline__ void fma2(unsigned long long& d, unsigned long long a, unsigned long long b) {
    asm("fma.rn.f32x2 %0, %1, %2, %0;" : "+l"(d) : "l"(a), "l"(b));
}
__device__ __forceinline__ void unpack2(unsigned long long v, float& lo, float& hi) {
    asm("mov.b64 {%0, %1}, %2;" : "=f"(lo), "=f"(hi) : "l"(v));
}

// ---------------- cp.async helpers ----------------
__device__ __forceinline__ void cpasync16(unsigned saddr, const void* g, int srcsz) {
    asm volatile("cp.async.cg.shared.global [%0], [%1], 16, %2;"
                 :: "r"(saddr), "l"(g), "r"(srcsz));
}
__device__ __forceinline__ void cp_commit() { asm volatile("cp.async.commit_group;"); }
template <int n> __device__ __forceinline__ void cp_wait() {
    asm volatile("cp.async.wait_group %0;" :: "n"(n));
}

// Stage 32 rows x NCOL cols of W (rows [k0,k0+32), zero-fill past K) into smem.
template <int NCOL>
__device__ __forceinline__ void stageW(float* ws, const float* __restrict__ Wg,
                                       int k0, int K, int tid) {
#pragma unroll
    for (int i = 0; i < NCOL / 32; i++) {
        int row, col;
        if (NCOL == 256) { row = (tid >> 6) + 4 * i; col = (tid & 63) * 4; }
        else             { row = (tid >> 5) + 8 * i; col = (tid & 31) * 4; }
        int gr = k0 + row;
        int sz = (gr < K) ? 16 : 0;
        const float* g = Wg + (size_t)((gr < K) ? gr : 0) * NCOL + col;
        unsigned sa = (unsigned)__cvta_generic_to_shared(ws + row * NCOL + col);
        cpasync16(sa, g, sz);
    }
}

// One dense layer over a 64-point tile.
// out[64][NCOL] = act( sum_seg srcT @ W + bias ),  written transposed to dstT.
// Thread map: warp w -> rows 8w..8w+7 ; lane l -> cols {l, l+32, ...}.
template <int NCOL>
__device__ __noinline__ void dense_layer(
    float* sm,
    const float* s1, int K1, const float* W1,
    const float* s2, int K2, const float* W2,
    const float* __restrict__ bias, int act, float* dstT)
{
    const int tid = threadIdx.x;
    const int w = tid >> 5, l = tid & 31;
    float* Ws = sm + SM_WS;
    constexpr int NPC = NCOL / 32;

    unsigned long long acc[4][NPC];
#pragma unroll
    for (int a = 0; a < NPC; a++) {
        unsigned long long b = dup2(bias[l + 32 * a]);
        acc[0][a] = b; acc[1][a] = b; acc[2][a] = b; acc[3][a] = b;
    }

#pragma unroll 1
    for (int s = 0; s < 2; s++) {
        const float* src = s ? s2 : s1;
        int K          = s ? K2 : K1;
        const float* Wg = s ? W2 : W1;
        if (K == 0) continue;
        int nch = (K + 31) >> 5;

        stageW<NCOL>(Ws, Wg, 0, K, tid);
        cp_commit();

#pragma unroll 1
        for (int c = 0; c < nch; c++) {
            const float* Wb = Ws + (c & 1) * (32 * NCOL);
            if (c + 1 < nch) {
                stageW<NCOL>(Ws + ((c + 1) & 1) * (32 * NCOL), Wg, (c + 1) * 32, K, tid);
                cp_commit();
                cp_wait<1>();
            } else {
                cp_wait<0>();
            }
            __syncthreads();

            int kend = K - c * 32; if (kend > 32) kend = 32;
            const float* xp = src + (size_t)(c * 32) * RS + 8 * w;
#pragma unroll 4
            for (int kk = 0; kk < kend; kk++) {
                ulonglong2 q0 = *(const ulonglong2*)(xp);
                ulonglong2 q1 = *(const ulonglong2*)(xp + 4);
                xp += RS;
                const float* wr = Wb + kk * NCOL + l;
#pragma unroll
                for (int a = 0; a < NPC; a++) {
                    unsigned long long wd = dup2(wr[32 * a]);
                    fma2(acc[0][a], q0.x, wd);
                    fma2(acc[1][a], q0.y, wd);
                    fma2(acc[2][a], q1.x, wd);
                    fma2(acc[3][a], q1.y, wd);
                }
            }
            __syncthreads();
        }
    }

    // writeback transposed (conflict-free float4: 4l mod 32 distinct per 8-lane phase)
#pragma unroll
    for (int a = 0; a < NPC; a++) {
        float v[8];
        unpack2(acc[0][a], v[0], v[1]);
        unpack2(acc[1][a], v[2], v[3]);
        unpack2(acc[2][a], v[4], v[5]);
        unpack2(acc[3][a], v[6], v[7]);
        if (act) {
#pragma unroll
            for (int q = 0; q < 8; q++) v[q] = fmaxf(v[q], 0.f);
        }
        float* d = dstT + (size_t)(l + 32 * a) * RS + 8 * w;
        *(float4*)(d)     = make_float4(v[0], v[1], v[2], v[3]);
        *(float4*)(d + 4) = make_float4(v[4], v[5], v[6], v[7]);
    }
    __syncthreads();
}

// ---------------- pass 0/1: zero + routing ----------------
__global__ void k_zero() { if (threadIdx.x < 8) g_cnt[threadIdx.x] = 0; }

__global__ void k_route(const float* __restrict__ pts, float* __restrict__ out) {
    int i = blockIdx.x * blockDim.x + threadIdx.x;
    if (i >= NPTS) return;
    float x = pts[3 * i], y = pts[3 * i + 1], z = pts[3 * i + 2];
    bool fg = (x >= -80.f) && (x <= 80.f) && (y >= -80.f) && (y <= 80.f)
           && (z >= -4.f) && (z <= 44.f);
    if (!fg) {
        out[i] = 0.f;
        out[NPTS + 3 * i] = 0.f; out[NPTS + 3 * i + 1] = 0.f; out[NPTS + 3 * i + 2] = 0.f;
        return;
    }
    int jx = (x > 0.f) ? 1 : 0;
    int iy = (y > 50.f) ? 3 : (y > 0.f) ? 2 : (y > -50.f) ? 1 : 0;
    int e = iy * 2 + jx;
    int pos = atomicAdd(&g_cnt[e], 1);
    g_list[e * NPTS + pos] = i;
}

// ---------------- pass 2: full MLP per (expert, tile) ----------------
__global__ void __launch_bounds__(256, 1) k_mlp(
    const float* __restrict__ pts, const float* __restrict__ vds,
    const int* __restrict__ aidx, const float* __restrict__ app,
    const float* __restrict__ W0, const float* __restrict__ b0,
    const float* __restrict__ Wpre, const float* __restrict__ bpre,
    const float* __restrict__ Wskip, const float* __restrict__ bskip,
    const float* __restrict__ Wpost, const float* __restrict__ bpost,
    const float* __restrict__ Wd, const float* __restrict__ bd,
    const float* __restrict__ Wf, const float* __restrict__ bf,
    const float* __restrict__ Wc1, const float* __restrict__ bc1,
    const float* __restrict__ Wc2, const float* __restrict__ bc2,
    float* __restrict__ out)
{
    const int e = blockIdx.y;
    const int cnt = g_cnt[e];
    const int base = blockIdx.x * TILE;
    if (base >= cnt) return;
    const int npts = min(TILE, cnt - base);

    extern __shared__ float sm[];
    float* xsT  = sm + SM_XST;
    float* x0T  = sm + SM_X0T;
    float* deT  = sm + SM_DET;
    float* WdS  = sm + SM_WD;
    float* Wc2S = sm + SM_WC2;
    float* dens = sm + SM_DENS;
    int*   gidx = (int*)(sm + SM_GIDX);

    const int tid = threadIdx.x;

    // ---- setup: posenc / appearance / direnc / small weights ----
    if (tid < 64) {
        int pt = tid;
        if (pt < npts) {
            int g = g_list[e * NPTS + base + pt];
            gidx[pt] = g;
            float px = pts[3 * g], py = pts[3 * g + 1], pz = pts[3 * g + 2];
            x0T[0 * RS + pt] = px; x0T[1 * RS + pt] = py; x0T[2 * RS + pt] = pz;
#pragma unroll 1
            for (int i = 0; i < 10; i++) {
                float f = (float)exp2((double)i * (10.0 / 9.0));   // match numpy f64->f32
                int r = 3 + 6 * i;
                double ax = (double)(f * px), ay = (double)(f * py), az = (double)(f * pz);
                x0T[(r + 0) * RS + pt] = (float)sin(ax);
                x0T[(r + 1) * RS + pt] = (float)sin(ay);
                x0T[(r + 2) * RS + pt] = (float)sin(az);
                x0T[(r + 3) * RS + pt] = (float)cos(ax);
                x0T[(r + 4) * RS + pt] = (float)cos(ay);
                x0T[(r + 5) * RS + pt] = (float)cos(az);
            }
        } else {
            gidx[pt] = 0;
#pragma unroll 1
            for (int r = 0; r < 63; r++) x0T[r * RS + pt] = 0.f;
        }
    } else if (tid < 128) {
        int pt = tid - 64;
        if (pt < npts) {
            int g = g_list[e * NPTS + base + pt];
            int ai = aidx[g];
            const float* a = app + ((size_t)e * 1000 + ai) * 48;
#pragma unroll 1
            for (int j = 0; j < 48; j++) x0T[(63 + j) * RS + pt] = a[j];
        } else {
#pragma unroll 1
            for (int j = 0; j < 48; j++) x0T[(63 + j) * RS + pt] = 0.f;
        }
    } else if (tid < 192) {
        int pt = tid - 128;
        if (pt < npts) {
            int g = g_list[e * NPTS + base + pt];
            float vx = vds[3 * g], vy = vds[3 * g + 1], vz = vds[3 * g + 2];
            deT[0 * RS + pt] = vx; deT[1 * RS + pt] = vy; deT[2 * RS + pt] = vz;
#pragma unroll 1
            for (int i = 0; i < 4; i++) {
                float f = (float)exp2((double)i * (4.0 / 3.0));
                int r = 3 + 6 * i;
                double ax = (double)(f * vx), ay = (double)(f * vy), az = (double)(f * vz);
                deT[(r + 0) * RS + pt] = (float)sin(ax);
                deT[(r + 1) * RS + pt] = (float)sin(ay);
                deT[(r + 2) * RS + pt] = (float)sin(az);
                deT[(r + 3) * RS + pt] = (float)cos(ax);
                deT[(r + 4) * RS + pt] = (float)cos(ay);
                deT[(r + 5) * RS + pt] = (float)cos(az);
            }
        } else {
#pragma unroll 1
            for (int r = 0; r < 27; r++) deT[r * RS + pt] = 0.f;
        }
    } else {
        int t = tid - 192;
        for (int j = t; j < 256; j += 64) WdS[j] = Wd[e * 256 + j];
        for (int j = t; j < 384; j += 64) Wc2S[j] = Wc2[e * 384 + j];
        if (t < 3) Wc2S[384 + t] = bc2[e * 3 + t];
    }
    __syncthreads();

    // ---- trunk ----
    dense_layer<256>(sm, x0T, 111, W0 + (size_t)e * 111 * 256,
                     nullptr, 0, nullptr, b0 + e * 256, 1, xsT);
#pragma unroll 1
    for (int i = 0; i < 3; i++)
        dense_layer<256>(sm, xsT, 256, Wpre + ((size_t)e * 3 + i) * 65536,
                         nullptr, 0, nullptr, bpre + (e * 3 + i) * 256, 1, xsT);
    dense_layer<256>(sm, xsT, 256, Wskip + (size_t)e * 367 * 256,
                     x0T, 111, Wskip + (size_t)e * 367 * 256 + 256 * 256,
                     bskip + e * 256, 1, xsT);
#pragma unroll 1
    for (int i = 0; i < 3; i++)
        dense_layer<256>(sm, xsT, 256, Wpost + ((size_t)e * 3 + i) * 65536,
                         nullptr, 0, nullptr, bpost + (e * 3 + i) * 256, 1, xsT);

    // ---- density: warp w handles points 8w..8w+7 ----
    {
        int w = tid >> 5, l = tid & 31;
        float bde = bd[e];
#pragma unroll 1
        for (int r = 0; r < 8; r++) {
            int pt = 8 * w + r;
            float s = 0.f;
#pragma unroll
            for (int j = 0; j < 8; j++) { int k = l + 32 * j; s += xsT[k * RS + pt] * WdS[k]; }
#pragma unroll
            for (int off = 16; off > 0; off >>= 1) s += __shfl_xor_sync(0xffffffffu, s, off);
            if (l == 0) dens[pt] = fmaxf(s + bde, 0.f);
        }
    }
    __syncthreads();

    // ---- feature (no relu) ----
    dense_layer<256>(sm, xsT, 256, Wf + (size_t)e * 65536,
                     nullptr, 0, nullptr, bf + e * 256, 0, xsT);

    // ---- color hidden (relu) -> xsT rows 0..127 ----
    dense_layer<128>(sm, xsT, 256, Wc1 + (size_t)e * 283 * 128,
                     deT, 27, Wc1 + (size_t)e * 283 * 128 + 256 * 128,
                     bc1 + e * 128, 1, xsT);

    // ---- color output + writes ----
    if (tid < 192) {
        int pt = tid / 3, cc = tid - 3 * pt;
        float s = Wc2S[384 + cc];
#pragma unroll 8
        for (int k = 0; k < 128; k++) s += xsT[k * RS + pt] * Wc2S[k * 3 + cc];
        if (pt < npts) {
            float col = 1.f / (1.f + expf(-s));
            out[NPTS + 3 * gidx[pt] + cc] = col;
        }
    }
    if (tid < 64 && tid < npts) out[gidx[tid]] = dens[tid];
}

// ---------------- launch ----------------
extern "C" void kernel_launch(void* const* d_in, const int* in_sizes, int n_in,
                              void* d_out, int out_size) {
    const float* pts   = (const float*)d_in[0];
    const float* vds   = (const float*)d_in[1];
    const int*   aidx  = (const int*)d_in[2];
    const float* app   = (const float*)d_in[3];
    const float* W0    = (const float*)d_in[4];
    const float* b0    = (const float*)d_in[5];
    const float* Wpre  = (const float*)d_in[6];
    const float* bpre  = (const float*)d_in[7];
    const float* Wskip = (const float*)d_in[8];
    const float* bskip = (const float*)d_in[9];
    const float* Wpost = (const float*)d_in[10];
    const float* bpost = (const float*)d_in[11];
    const float* Wd    = (const float*)d_in[12];
    const float* bd    = (const float*)d_in[13];
    const float* Wf    = (const float*)d_in[14];
    const float* bf    = (const float*)d_in[15];
    const float* Wc1   = (const float*)d_in[16];
    const float* bc1   = (const float*)d_in[17];
    const float* Wc2   = (const float*)d_in[18];
    const float* bc2   = (const float*)d_in[19];
    float* out = (float*)d_out;

    static bool attr_done = false;
    if (!attr_done) {
        cudaFuncSetAttribute(k_mlp, cudaFuncAttributeMaxDynamicSharedMemorySize, SMEM_BYTES);
        attr_done = true;
    }

    k_zero<<<1, 32>>>();
    k_route<<<NPTS / 256, 256>>>(pts, out);
    dim3 grid(NPTS / TILE, 8);  // 512 tiles x 8 experts; empty tiles exit
    k_mlp<<<grid, 256, SMEM_BYTES>>>(pts, vds, aidx, app, W0, b0, Wpre, bpre,
                                     Wskip, bskip, Wpost, bpost, Wd, bd, Wf, bf,
                                     Wc1, bc1, Wc2, bc2, out);
}